// round 14
// baseline (speedup 1.0000x reference)
#include <cuda_runtime.h>
#include <cstdint>

// Problem shape (fixed by the dataset): B=512, S=1024, T=64
#define Bn 512
#define Sn 1024
#define Tn 64
#define WPB 4          // forward warps per block; each warp runs TWO chains
#define FWD_BLOCKS 64  // 64 blocks x 4 warps x 2 chains = 512
#define GOLD_BLOCKS 16 // gold on otherwise-idle SMs

typedef unsigned long long u64;

__device__ float g_z[Bn];
__device__ float g_sc[Bn];

__device__ __forceinline__ u64 ffma2(u64 a, u64 b, u64 c) {
    u64 d;
    asm("fma.rn.f32x2 %0, %1, %2, %3;" : "=l"(d) : "l"(a), "l"(b), "l"(c));
    return d;
}
__device__ __forceinline__ u64 fadd2(u64 a, u64 b) {
    u64 d;
    asm("add.rn.f32x2 %0, %1, %2;" : "=l"(d) : "l"(a), "l"(b));
    return d;
}
__device__ __forceinline__ u64 fmul2(u64 a, u64 b) {
    u64 d;
    asm("mul.rn.f32x2 %0, %1, %2;" : "=l"(d) : "l"(a), "l"(b));
    return d;
}
__device__ __forceinline__ u64 pk2(float a, float b) {
    u64 d;
    asm("mov.b64 %0, {%1,%2};" : "=l"(d) : "f"(a), "f"(b));
    return d;
}
__device__ __forceinline__ float2 upk(u64 p) {
    float2 r;
    asm("mov.b64 {%0,%1}, %2;" : "=f"(r.x), "=f"(r.y) : "l"(p));
    return r;
}

// ---------------------------------------------------------------------------
// Forward recursion (blocks 0..63), linear domain, TWO LEAN CHAINS PER WARP:
//   s_{t+1}[j] = (sum_i s_t[i] * E[i][j]) * exp(e_t[j]),  E = exp(trans)
// One warp per SMSP; the warp interleaves two independent batch chains so
// chain B's FFMA2 stream fills chain A's head/tail latency (one shared
// syncwarp head per superstep). LEAN register budget (R13 spilled):
// shared E tiles (128 regs), 8 u64 accumulators, eraw depth 4 per chain
// (~190 regs total). Thread c owns columns (2c, 2c+1) of both chains.
// Renorm every 8 steps by 2^-ke from the exponent bits of s[0].
// Gold scores: blocks 64..79 on idle SMs.
// ---------------------------------------------------------------------------
__global__ __launch_bounds__(32 * WPB, 1) void crf_fused(
    const float* __restrict__ em,    // [B, S, T]
    const int*   __restrict__ tags,  // [B, S]
    const float* __restrict__ mask,  // [B, S]
    const float* __restrict__ tr)    // [T, T]
{
    const int w    = threadIdx.x >> 5;
    const int lane = threadIdx.x & 31;

    if (blockIdx.x >= FWD_BLOCKS) {
        // ------- gold blocks: 4 warps/block, 8 batches per warp -------
        const int gw = (blockIdx.x - FWD_BLOCKS) * WPB + w;  // 0..63
        for (int k = 0; k < 8; k++) {
            const int b = gw * 8 + k;
            const int* tg = tags + b * Sn;
            const float* eb = em + (size_t)b * Sn * Tn;
            float acc = 0.0f;
            for (int sx = 1 + lane; sx < Sn; sx += 32) {
                int   t1  = __ldg(tg + sx);
                int   t0  = __ldg(tg + sx - 1);
                float mt  = __ldg(mask + b * Sn + sx);
                float emv = __ldg(eb + (size_t)sx * Tn + t1);
                float trv = __ldg(tr + t0 * Tn + t1);
                acc += (emv + trv) * mt;
            }
#pragma unroll
            for (int o = 16; o; o >>= 1)
                acc += __shfl_xor_sync(0xffffffffu, acc, o);
            if (lane == 0) g_sc[b] = acc;
        }
        return;
    }

    // ---------------- forward: warp w owns batches bA, bB ----------------
    const int c  = lane;                          // column pair (2c, 2c+1)
    const int gb = blockIdx.x * WPB + w;          // global warp id 0..255
    const int bA = 2 * gb;
    const int bB = 2 * gb + 1;

    __shared__ __align__(16) u64 sbuf[WPB][2][2][32]; // [warp][chain][buf][c]
    __shared__ float mA_[WPB][Sn];                    // mask rows (plain f32)
    __shared__ float mB_[WPB][Sn];

    for (int i = c; i < Sn; i += 32) {
        mA_[w][i] = mask[bA * Sn + i];
        mB_[w][i] = mask[bB * Sn + i];
    }

    // Shared E register tiles: EA[p] = (E[2p][2c], E[2p+1][2c]), EB col 2c+1
    u64 EA[32], EB[32];
#pragma unroll
    for (int p = 0; p < 32; p++) {
        EA[p] = pk2(__expf(tr[(2 * p) * Tn + 2 * c]),
                    __expf(tr[(2 * p + 1) * Tn + 2 * c]));
        EB[p] = pk2(__expf(tr[(2 * p) * Tn + 2 * c + 1]),
                    __expf(tr[(2 * p + 1) * Tn + 2 * c + 1]));
    }

    // Emission streams: raw float2, prefetch depth 4 per chain (lean regs;
    // 4 steps x ~235 cyc >> DRAM 577 cyc)
    const float2* epA = (const float2*)(em + (size_t)bA * Sn * Tn) + c;
    const float2* epB = (const float2*)(em + (size_t)bB * Sn * Tn) + c;
    float2 erA[4], erB[4];
#pragma unroll
    for (int d = 0; d < 4; d++) { erA[d] = __ldg(epA + d * 32);
                                  erB[d] = __ldg(epB + d * 32); }

    u64 sA = pk2(1.0f, 1.0f), sB = pk2(1.0f, 1.0f);
    int okA = 0, okB = 0;
    __syncwarp();

    for (int tb = 0; tb < Sn; tb += 8) {
#pragma unroll
        for (int u = 0; u < 8; u++) {
            const int t   = tb + u;
            const int par = u & 1;
            const int sl  = u & 3;

            // publish both chains' pairs; one sync covers both
            sbuf[w][0][par][c] = sA;
            sbuf[w][1][par][c] = sB;

            // independent work rides the sync window
            float mA = mA_[w][t], mB = mB_[w][t];
            float2 eA = erA[sl], eB = erB[sl];
            u64 fA = pk2(__expf(eA.x), __expf(eA.y));
            u64 fB = pk2(__expf(eB.x), __expf(eB.y));
            if (t + 4 < Sn) { erA[sl] = __ldg(epA + (size_t)(t + 4) * 32);
                              erB[sl] = __ldg(epB + (size_t)(t + 4) * 32); }

            __syncwarp();

            // interleaved matvecs: 32 LDS.128, 128 FFMA2, 8 lean acc chains
            const u64* svA = &sbuf[w][0][par][0];
            const u64* svB = &sbuf[w][1][par][0];
            u64 aA0 = 0, aA1 = 0, bA0 = 0, bA1 = 0;
            u64 aB0 = 0, aB1 = 0, bB0 = 0, bB1 = 0;
            u64 v0A, v0B;
#pragma unroll
            for (int p = 0; p < 32; p += 2) {
                ulonglong2 xA = *(const ulonglong2*)&svA[p];
                ulonglong2 xB = *(const ulonglong2*)&svB[p];
                if (p == 0) { v0A = xA.x; v0B = xB.x; }
                aA0 = ffma2(xA.x, EA[p + 0], aA0);
                bA0 = ffma2(xA.x, EB[p + 0], bA0);
                aB0 = ffma2(xB.x, EA[p + 0], aB0);
                bB0 = ffma2(xB.x, EB[p + 0], bB0);
                aA1 = ffma2(xA.y, EA[p + 1], aA1);
                bA1 = ffma2(xA.y, EB[p + 1], bA1);
                aB1 = ffma2(xB.y, EA[p + 1], aB1);
                bB1 = ffma2(xB.y, EB[p + 1], bB1);
            }
            // chain A tail (overlaps chain B's FFMA stream in issue order)
            {
                u64 sa = fadd2(aA0, aA1);
                u64 sb = fadd2(bA0, bA1);
                float2 fa = upk(sa), fb = upk(sb);
                u64 qf = fmul2(pk2(fa.x + fa.y, fb.x + fb.y), fA);
                float om = 1.0f - mA;
                u64 sn = ffma2(pk2(om, om), sA, fmul2(pk2(mA, mA), qf));
                if (u == 7) {
                    int ke = ((__float_as_int(upk(v0A).x) >> 23) & 0xff) - 127;
                    okA += ke;
                    float sc = __int_as_float((127 - ke) << 23);
                    sn = fmul2(sn, pk2(sc, sc));
                }
                sA = sn;
            }
            // chain B tail
            {
                u64 sa = fadd2(aB0, aB1);
                u64 sb = fadd2(bB0, bB1);
                float2 fa = upk(sa), fb = upk(sb);
                u64 qf = fmul2(pk2(fa.x + fa.y, fb.x + fb.y), fB);
                float om = 1.0f - mB;
                u64 sn = ffma2(pk2(om, om), sB, fmul2(pk2(mB, mB), qf));
                if (u == 7) {
                    int ke = ((__float_as_int(upk(v0B).x) >> 23) & 0xff) - 127;
                    okB += ke;
                    float sc = __int_as_float((127 - ke) << 23);
                    sn = fmul2(sn, pk2(sc, sc));
                }
                sB = sn;
            }
        }
    }

    // z[b] = offk*ln2 + log(sum_j s[j]) for both chains
    float2 pA = upk(sA), pB = upk(sB);
    float xA = pA.x + pA.y, xB = pB.x + pB.y;
#pragma unroll
    for (int o = 16; o; o >>= 1) {
        xA += __shfl_xor_sync(0xffffffffu, xA, o);
        xB += __shfl_xor_sync(0xffffffffu, xB, o);
    }
    if (lane == 0) {
        g_z[bA] = (float)((double)okA * 0.6931471805599453 + (double)logf(xA));
        g_z[bB] = (float)((double)okB * 0.6931471805599453 + (double)logf(xB));
    }
}

// ---------------------------------------------------------------------------
// out = -mean(z - score)
// ---------------------------------------------------------------------------
__global__ __launch_bounds__(Bn) void crf_final(float* __restrict__ out)
{
    __shared__ float red[Bn];
    const int tid = threadIdx.x;
    red[tid] = g_z[tid] - g_sc[tid];
    __syncthreads();
    for (int st = Bn / 2; st; st >>= 1) {
        if (tid < st) red[tid] += red[tid + st];
        __syncthreads();
    }
    if (tid == 0) out[0] = -red[0] / (float)Bn;
}

extern "C" void kernel_launch(void* const* d_in, const int* in_sizes, int n_in,
                              void* d_out, int out_size)
{
    const float* em   = (const float*)d_in[0];  // emissions [B,S,T] f32
    const int*   tags = (const int*)  d_in[1];  // tags [B,S] i32
    const float* mask = (const float*)d_in[2];  // mask [B,S] f32
    const float* tr   = (const float*)d_in[3];  // transitions [T,T] f32

    crf_fused<<<FWD_BLOCKS + GOLD_BLOCKS, 32 * WPB>>>(em, tags, mask, tr);
    crf_final<<<1, Bn>>>((float*)d_out);
}

// round 15
// speedup vs baseline: 2.3020x; 2.3020x over previous
#include <cuda_runtime.h>
#include <cstdint>

// Problem shape (fixed by the dataset): B=512, S=1024, T=64
#define Bn 512
#define Sn 1024
#define Tn 64
#define WPB 4          // forward warps per block: one chain-warp per SMSP
#define FWD_BLOCKS 128 // blocks 0..127: forward (512 chains, 1/SMSP)
#define GOLD_BLOCKS 16 // blocks 128..143: gold scores on idle SMs

typedef unsigned long long u64;

__device__ float g_z[Bn];
__device__ float g_sc[Bn];

__device__ __forceinline__ u64 ffma2(u64 a, u64 b, u64 c) {
    u64 d;
    asm("fma.rn.f32x2 %0, %1, %2, %3;" : "=l"(d) : "l"(a), "l"(b), "l"(c));
    return d;
}
__device__ __forceinline__ u64 fadd2(u64 a, u64 b) {
    u64 d;
    asm("add.rn.f32x2 %0, %1, %2;" : "=l"(d) : "l"(a), "l"(b));
    return d;
}
__device__ __forceinline__ u64 fmul2(u64 a, u64 b) {
    u64 d;
    asm("mul.rn.f32x2 %0, %1, %2;" : "=l"(d) : "l"(a), "l"(b));
    return d;
}
__device__ __forceinline__ u64 pk2(float a, float b) {
    u64 d;
    asm("mov.b64 %0, {%1,%2};" : "=l"(d) : "f"(a), "f"(b));
    return d;
}
__device__ __forceinline__ float2 upk(u64 p) {
    float2 r;
    asm("mov.b64 {%0,%1}, %2;" : "=f"(r.x), "=f"(r.y) : "l"(p));
    return r;
}

// ---------------------------------------------------------------------------
// Forward recursion (blocks 0..127), linear domain, ONE WARP PER CHAIN,
// one chain-warp per SMSP. s-vector exchange by SHFL.IDX register broadcast
// (no smem, no syncwarp, no double buffer):
//   s_{t+1}[j] = (sum_i s_t[i] * E[i][j]) * exp(e_t[j]),  E = exp(trans)
// Lane c owns columns (2c, 2c+1); pair p of the s-vector is fetched with two
// shfl.sync from lane p and consumed by two FFMA2 (cols A and B). SHFLs ride
// the MIO pipe inside the 192-cycle FFMA2 issue stream. Renorm every 8 steps
// by 2^-ke from the exponent bits of s[0] (the p=0 shfl result).
// Gold scores (blocks 128..143) run on SMs the forward grid leaves idle.
// ---------------------------------------------------------------------------
__global__ __launch_bounds__(32 * WPB, 1) void crf_fused(
    const float* __restrict__ em,    // [B, S, T]
    const int*   __restrict__ tags,  // [B, S]
    const float* __restrict__ mask,  // [B, S]
    const float* __restrict__ tr)    // [T, T]
{
    const int w    = threadIdx.x >> 5;
    const int lane = threadIdx.x & 31;

    if (blockIdx.x >= FWD_BLOCKS) {
        // ------- gold blocks: 4 warps/block, 8 batches per warp -------
        const int gw = (blockIdx.x - FWD_BLOCKS) * WPB + w;  // 0..63
        for (int k = 0; k < 8; k++) {
            const int b = gw * 8 + k;
            const int* tg = tags + b * Sn;
            const float* eb = em + (size_t)b * Sn * Tn;
            float acc = 0.0f;
            for (int sx = 1 + lane; sx < Sn; sx += 32) {
                int   t1  = __ldg(tg + sx);
                int   t0  = __ldg(tg + sx - 1);
                float mt  = __ldg(mask + b * Sn + sx);
                float emv = __ldg(eb + (size_t)sx * Tn + t1);
                float trv = __ldg(tr + t0 * Tn + t1);
                acc += (emv + trv) * mt;
            }
#pragma unroll
            for (int o = 16; o; o >>= 1)
                acc += __shfl_xor_sync(0xffffffffu, acc, o);
            if (lane == 0) g_sc[b] = acc;
        }
        return;
    }

    // ---------------- forward: warp w owns batch b ----------------
    const int c = lane;                        // column pair (2c, 2c+1)
    const int b = blockIdx.x * WPB + w;

    __shared__ float2 mrow[WPB][Sn];           // (m, 1-m) per step

    // Stage mask row (warp-private region; no block sync needed)
    for (int i = c; i < Sn; i += 32) {
        float m = mask[b * Sn + i];
        mrow[w][i] = make_float2(m, 1.0f - m);
    }

    // E register tiles: EA[p] = (E[2p][2c], E[2p+1][2c]), EB for col 2c+1
    u64 EA[32], EB[32];
#pragma unroll
    for (int p = 0; p < 32; p++) {
        EA[p] = pk2(__expf(tr[(2 * p) * Tn + 2 * c]),
                    __expf(tr[(2 * p + 1) * Tn + 2 * c]));
        EB[p] = pk2(__expf(tr[(2 * p) * Tn + 2 * c + 1]),
                    __expf(tr[(2 * p + 1) * Tn + 2 * c + 1]));
    }

    // Emission stream: raw float2 loaded 8 steps ahead; exp'd at step top
    const float2* ep = (const float2*)(em + (size_t)b * Sn * Tn) + c;
    float2 eraw[8];
#pragma unroll
    for (int d = 0; d < 8; d++) eraw[d] = __ldg(ep + d * 32);

    // s pair held in registers (lane c owns s[2c], s[2c+1])
    float sx = 1.0f, sy = 1.0f;
    int offk = 0;
    __syncwarp();   // mask staging visible to the warp (own writes anyway)

    for (int tb = 0; tb < Sn; tb += 8) {
#pragma unroll
        for (int u = 0; u < 8; u++) {
            const int t = tb + u;

            // off-chain work first (independent of this step's exchange)
            float2 mm = mrow[w][t];
            float2 er = eraw[u];
            u64 f = pk2(__expf(er.x), __expf(er.y));
            if (t + 8 < Sn) eraw[u] = __ldg(ep + (size_t)(t + 8) * 32);

            // matvec via register exchange: 64 SHFL + 64 FFMA2, 4 acc chains
            u64 a0 = 0, a1 = 0, b0 = 0, b1 = 0;
            float v00;   // s[0] for the renorm (lane-0 broadcast of pair 0)
#pragma unroll
            for (int p = 0; p < 32; p += 2) {
                float lo0 = __shfl_sync(0xffffffffu, sx, p);
                float hi0 = __shfl_sync(0xffffffffu, sy, p);
                float lo1 = __shfl_sync(0xffffffffu, sx, p + 1);
                float hi1 = __shfl_sync(0xffffffffu, sy, p + 1);
                u64 v0 = pk2(lo0, hi0);
                u64 v1 = pk2(lo1, hi1);
                if (p == 0) v00 = lo0;
                a0 = ffma2(v0, EA[p + 0], a0);
                b0 = ffma2(v0, EB[p + 0], b0);
                a1 = ffma2(v1, EA[p + 1], a1);
                b1 = ffma2(v1, EB[p + 1], b1);
            }
            u64 sa = fadd2(a0, a1);
            u64 sb = fadd2(b0, b1);
            float2 fa = upk(sa), fb = upk(sb);
            u64 qf = fmul2(pk2(fa.x + fa.y, fb.x + fb.y), f);

            // masked blend: s = m*qf + (1-m)*s
            u64 sold = pk2(sx, sy);
            u64 sn = ffma2(pk2(mm.y, mm.y), sold, fmul2(pk2(mm.x, mm.x), qf));

            // renorm every 8 steps by 2^-ke, ke from exponent of s[0]
            if (u == 7) {
                int ke = ((__float_as_int(v00) >> 23) & 0xff) - 127;
                offk += ke;
                float sc = __int_as_float((127 - ke) << 23);
                sn = fmul2(sn, pk2(sc, sc));
            }
            float2 snf = upk(sn);
            sx = snf.x; sy = snf.y;
        }
    }

    // z[b] = offk*ln2 + log(sum_j s[j])
    float x = sx + sy;
#pragma unroll
    for (int o = 16; o; o >>= 1)
        x += __shfl_xor_sync(0xffffffffu, x, o);
    if (lane == 0) {
        double z = (double)offk * 0.6931471805599453 + (double)logf(x);
        g_z[b] = (float)z;
    }
}

// ---------------------------------------------------------------------------
// out = -mean(z - score)
// ---------------------------------------------------------------------------
__global__ __launch_bounds__(Bn) void crf_final(float* __restrict__ out)
{
    __shared__ float red[Bn];
    const int tid = threadIdx.x;
    red[tid] = g_z[tid] - g_sc[tid];
    __syncthreads();
    for (int st = Bn / 2; st; st >>= 1) {
        if (tid < st) red[tid] += red[tid + st];
        __syncthreads();
    }
    if (tid == 0) out[0] = -red[0] / (float)Bn;
}

extern "C" void kernel_launch(void* const* d_in, const int* in_sizes, int n_in,
                              void* d_out, int out_size)
{
    const float* em   = (const float*)d_in[0];  // emissions [B,S,T] f32
    const int*   tags = (const int*)  d_in[1];  // tags [B,S] i32
    const float* mask = (const float*)d_in[2];  // mask [B,S] f32
    const float* tr   = (const float*)d_in[3];  // transitions [T,T] f32

    crf_fused<<<FWD_BLOCKS + GOLD_BLOCKS, 32 * WPB>>>(em, tags, mask, tr);
    crf_final<<<1, Bn>>>((float*)d_out);
}

// round 16
// speedup vs baseline: 2.9824x; 1.2955x over previous
#include <cuda_runtime.h>
#include <cstdint>

// Problem shape (fixed by the dataset): B=512, S=1024, T=64
#define Bn 512
#define Sn 1024
#define Tn 64
#define WPB 4          // forward warps per block: one chain-warp per SMSP
#define FWD_BLOCKS 128 // blocks 0..127: forward (512 chains, 1/SMSP)
#define GOLD_BLOCKS 16 // blocks 128..143: gold scores on idle SMs

typedef unsigned long long u64;

__device__ float g_z[Bn];
__device__ float g_sc[Bn];

__device__ __forceinline__ u64 ffma2(u64 a, u64 b, u64 c) {
    u64 d;
    asm("fma.rn.f32x2 %0, %1, %2, %3;" : "=l"(d) : "l"(a), "l"(b), "l"(c));
    return d;
}
__device__ __forceinline__ u64 fadd2(u64 a, u64 b) {
    u64 d;
    asm("add.rn.f32x2 %0, %1, %2;" : "=l"(d) : "l"(a), "l"(b));
    return d;
}
__device__ __forceinline__ u64 fmul2(u64 a, u64 b) {
    u64 d;
    asm("mul.rn.f32x2 %0, %1, %2;" : "=l"(d) : "l"(a), "l"(b));
    return d;
}
__device__ __forceinline__ u64 pk2(float a, float b) {
    u64 d;
    asm("mov.b64 %0, {%1,%2};" : "=l"(d) : "f"(a), "f"(b));
    return d;
}
__device__ __forceinline__ float2 upk(u64 p) {
    float2 r;
    asm("mov.b64 {%0,%1}, %2;" : "=f"(r.x), "=f"(r.y) : "l"(p));
    return r;
}

// ---------------------------------------------------------------------------
// Forward recursion (blocks 0..127), linear domain, ONE WARP PER CHAIN,
// one chain-warp per SMSP (R12 proven geometry), with the syncwarp removed:
//   s_{t+1}[j] = (sum_i s_t[i] * E[i][j]) * exp(e_t[j]),  E = exp(trans)
// Within a non-divergent warp the STS wavefront and the following LDS
// wavefronts of the SAME buffer are ordered by the SMSP LSU pipeline; the
// double buffer makes cross-step compiler reordering harmless (adjacent
// steps use disjoint buffers). Thread c owns columns (2c, 2c+1).
// 4 accumulators (short tail tree). Renorm every 8 steps by 2^-ke from the
// exponent bits of s[0]. Gold scores: blocks 128..143 on idle SMs.
// ---------------------------------------------------------------------------
__global__ __launch_bounds__(32 * WPB, 1) void crf_fused(
    const float* __restrict__ em,    // [B, S, T]
    const int*   __restrict__ tags,  // [B, S]
    const float* __restrict__ mask,  // [B, S]
    const float* __restrict__ tr)    // [T, T]
{
    const int w    = threadIdx.x >> 5;
    const int lane = threadIdx.x & 31;

    if (blockIdx.x >= FWD_BLOCKS) {
        // ------- gold blocks: 4 warps/block, 8 batches per warp -------
        const int gw = (blockIdx.x - FWD_BLOCKS) * WPB + w;  // 0..63
        for (int k = 0; k < 8; k++) {
            const int b = gw * 8 + k;
            const int* tg = tags + b * Sn;
            const float* eb = em + (size_t)b * Sn * Tn;
            float acc = 0.0f;
            for (int sx = 1 + lane; sx < Sn; sx += 32) {
                int   t1  = __ldg(tg + sx);
                int   t0  = __ldg(tg + sx - 1);
                float mt  = __ldg(mask + b * Sn + sx);
                float emv = __ldg(eb + (size_t)sx * Tn + t1);
                float trv = __ldg(tr + t0 * Tn + t1);
                acc += (emv + trv) * mt;
            }
#pragma unroll
            for (int o = 16; o; o >>= 1)
                acc += __shfl_xor_sync(0xffffffffu, acc, o);
            if (lane == 0) g_sc[b] = acc;
        }
        return;
    }

    // ---------------- forward: warp w owns batch b ----------------
    const int c = lane;                        // column pair (2c, 2c+1)
    const int b = blockIdx.x * WPB + w;

    __shared__ __align__(16) u64 sbuf[WPB][2][32];  // double-buffered s pairs
    __shared__ float2 mrow[WPB][Sn];                // (m, 1-m) per step

    // Stage mask row (warp-private region; no block sync needed)
    for (int i = c; i < Sn; i += 32) {
        float m = mask[b * Sn + i];
        mrow[w][i] = make_float2(m, 1.0f - m);
    }

    // E register tiles: EA[p] = (E[2p][2c], E[2p+1][2c]), EB for col 2c+1
    u64 EA[32], EB[32];
#pragma unroll
    for (int p = 0; p < 32; p++) {
        EA[p] = pk2(__expf(tr[(2 * p) * Tn + 2 * c]),
                    __expf(tr[(2 * p + 1) * Tn + 2 * c]));
        EB[p] = pk2(__expf(tr[(2 * p) * Tn + 2 * c + 1]),
                    __expf(tr[(2 * p + 1) * Tn + 2 * c + 1]));
    }

    // Emission stream: raw float2 loaded 8 steps ahead; exp'd at step top
    const float2* ep = (const float2*)(em + (size_t)b * Sn * Tn) + c;
    float2 eraw[8];
#pragma unroll
    for (int d = 0; d < 8; d++) eraw[d] = __ldg(ep + d * 32);

    u64 s    = pk2(1.0f, 1.0f);
    int offk = 0;
    __syncwarp();   // one-time: after staging, before the recursion

    for (int tb = 0; tb < Sn; tb += 8) {
#pragma unroll
        for (int u = 0; u < 8; u++) {
            const int t   = tb + u;
            const int par = u & 1;

            // publish own pair (LSU orders the following LDS of this buffer)
            sbuf[w][par][c] = s;

            // independent work covers the STS->LDS pipeline gap
            float2 mm = mrow[w][t];
            float2 er = eraw[u];
            u64 f = pk2(__expf(er.x), __expf(er.y));   // MUFU, used at tail
            if (t + 8 < Sn) eraw[u] = __ldg(ep + (size_t)(t + 8) * 32);

            // matvec for both columns: 16 LDS.128, 64 FFMA2 (4 acc chains)
            const u64* sv = &sbuf[w][par][0];
            u64 a0 = 0, a1 = 0, b0 = 0, b1 = 0;
            u64 v0pair;
#pragma unroll
            for (int p = 0; p < 32; p += 2) {
                ulonglong2 x = *(const ulonglong2*)&sv[p];
                if (p == 0) v0pair = x.x;
                a0 = ffma2(x.x, EA[p + 0], a0);
                b0 = ffma2(x.x, EB[p + 0], b0);
                a1 = ffma2(x.y, EA[p + 1], a1);
                b1 = ffma2(x.y, EB[p + 1], b1);
            }
            u64 sa = fadd2(a0, a1);
            u64 sb = fadd2(b0, b1);
            float2 fa = upk(sa), fb2 = upk(sb);
            u64 qf = fmul2(pk2(fa.x + fa.y, fb2.x + fb2.y), f);

            // masked blend: s = m*qf + (1-m)*s
            u64 sn = ffma2(pk2(mm.y, mm.y), s, fmul2(pk2(mm.x, mm.x), qf));

            // renorm every 8 steps by 2^-ke, ke from exponent of s[0]
            // (v0pair.x = published s[0], uniform across lanes)
            if (u == 7) {
                int ke = ((__float_as_int(upk(v0pair).x) >> 23) & 0xff) - 127;
                offk += ke;
                float sc = __int_as_float((127 - ke) << 23);
                sn = fmul2(sn, pk2(sc, sc));
            }
            s = sn;
        }
    }

    // z[b] = offk*ln2 + log(sum_j s[j])
    float2 sp = upk(s);
    float x = sp.x + sp.y;
#pragma unroll
    for (int o = 16; o; o >>= 1)
        x += __shfl_xor_sync(0xffffffffu, x, o);
    if (lane == 0) {
        double z = (double)offk * 0.6931471805599453 + (double)logf(x);
        g_z[b] = (float)z;
    }
}

// ---------------------------------------------------------------------------
// out = -mean(z - score)
// ---------------------------------------------------------------------------
__global__ __launch_bounds__(Bn) void crf_final(float* __restrict__ out)
{
    __shared__ float red[Bn];
    const int tid = threadIdx.x;
    red[tid] = g_z[tid] - g_sc[tid];
    __syncthreads();
    for (int st = Bn / 2; st; st >>= 1) {
        if (tid < st) red[tid] += red[tid + st];
        __syncthreads();
    }
    if (tid == 0) out[0] = -red[0] / (float)Bn;
}

extern "C" void kernel_launch(void* const* d_in, const int* in_sizes, int n_in,
                              void* d_out, int out_size)
{
    const float* em   = (const float*)d_in[0];  // emissions [B,S,T] f32
    const int*   tags = (const int*)  d_in[1];  // tags [B,S] i32
    const float* mask = (const float*)d_in[2];  // mask [B,S] f32
    const float* tr   = (const float*)d_in[3];  // transitions [T,T] f32

    crf_fused<<<FWD_BLOCKS + GOLD_BLOCKS, 32 * WPB>>>(em, tags, mask, tr);
    crf_final<<<1, Bn>>>((float*)d_out);
}

// round 17
// speedup vs baseline: 3.0059x; 1.0079x over previous
#include <cuda_runtime.h>
#include <cstdint>

// Problem shape (fixed by the dataset): B=512, S=1024, T=64
#define Bn 512
#define Sn 1024
#define Tn 64
#define WPB 4          // forward warps per block: one chain-warp per SMSP
#define FWD_BLOCKS 128 // blocks 0..127: forward (512 chains, 1/SMSP)
#define GOLD_BLOCKS 16 // blocks 128..143: gold scores on idle SMs

typedef unsigned long long u64;

__device__ float g_z[Bn];
__device__ float g_sc[Bn];

__device__ __forceinline__ u64 ffma2(u64 a, u64 b, u64 c) {
    u64 d;
    asm("fma.rn.f32x2 %0, %1, %2, %3;" : "=l"(d) : "l"(a), "l"(b), "l"(c));
    return d;
}
__device__ __forceinline__ u64 fadd2(u64 a, u64 b) {
    u64 d;
    asm("add.rn.f32x2 %0, %1, %2;" : "=l"(d) : "l"(a), "l"(b));
    return d;
}
__device__ __forceinline__ u64 fmul2(u64 a, u64 b) {
    u64 d;
    asm("mul.rn.f32x2 %0, %1, %2;" : "=l"(d) : "l"(a), "l"(b));
    return d;
}
__device__ __forceinline__ u64 pk2(float a, float b) {
    u64 d;
    asm("mov.b64 %0, {%1,%2};" : "=l"(d) : "f"(a), "f"(b));
    return d;
}
__device__ __forceinline__ float2 upk(u64 p) {
    float2 r;
    asm("mov.b64 {%0,%1}, %2;" : "=f"(r.x), "=f"(r.y) : "l"(p));
    return r;
}

// ---------------------------------------------------------------------------
// Forward recursion (blocks 0..127), linear domain, ONE WARP PER CHAIN,
// one chain-warp per SMSP (R12 proven geometry), with the syncwarp removed:
//   s_{t+1}[j] = (sum_i s_t[i] * E[i][j]) * exp(e_t[j]),  E = exp(trans)
// Within a non-divergent warp the STS wavefront and the following LDS
// wavefronts of the SAME buffer are ordered by the SMSP LSU pipeline; the
// double buffer makes cross-step compiler reordering harmless (adjacent
// steps use disjoint buffers). Thread c owns columns (2c, 2c+1).
// 4 accumulators (short tail tree). Renorm every 8 steps by 2^-ke from the
// exponent bits of s[0]. Gold scores: blocks 128..143 on idle SMs.
// ---------------------------------------------------------------------------
__global__ __launch_bounds__(32 * WPB, 1) void crf_fused(
    const float* __restrict__ em,    // [B, S, T]
    const int*   __restrict__ tags,  // [B, S]
    const float* __restrict__ mask,  // [B, S]
    const float* __restrict__ tr)    // [T, T]
{
    const int w    = threadIdx.x >> 5;
    const int lane = threadIdx.x & 31;

    if (blockIdx.x >= FWD_BLOCKS) {
        // ------- gold blocks: 4 warps/block, 8 batches per warp -------
        const int gw = (blockIdx.x - FWD_BLOCKS) * WPB + w;  // 0..63
        for (int k = 0; k < 8; k++) {
            const int b = gw * 8 + k;
            const int* tg = tags + b * Sn;
            const float* eb = em + (size_t)b * Sn * Tn;
            float acc = 0.0f;
            for (int sx = 1 + lane; sx < Sn; sx += 32) {
                int   t1  = __ldg(tg + sx);
                int   t0  = __ldg(tg + sx - 1);
                float mt  = __ldg(mask + b * Sn + sx);
                float emv = __ldg(eb + (size_t)sx * Tn + t1);
                float trv = __ldg(tr + t0 * Tn + t1);
                acc += (emv + trv) * mt;
            }
#pragma unroll
            for (int o = 16; o; o >>= 1)
                acc += __shfl_xor_sync(0xffffffffu, acc, o);
            if (lane == 0) g_sc[b] = acc;
        }
        return;
    }

    // ---------------- forward: warp w owns batch b ----------------
    const int c = lane;                        // column pair (2c, 2c+1)
    const int b = blockIdx.x * WPB + w;

    __shared__ __align__(16) u64 sbuf[WPB][2][32];  // double-buffered s pairs
    __shared__ float2 mrow[WPB][Sn];                // (m, 1-m) per step

    // Stage mask row (warp-private region; no block sync needed)
    for (int i = c; i < Sn; i += 32) {
        float m = mask[b * Sn + i];
        mrow[w][i] = make_float2(m, 1.0f - m);
    }

    // E register tiles: EA[p] = (E[2p][2c], E[2p+1][2c]), EB for col 2c+1
    u64 EA[32], EB[32];
#pragma unroll
    for (int p = 0; p < 32; p++) {
        EA[p] = pk2(__expf(tr[(2 * p) * Tn + 2 * c]),
                    __expf(tr[(2 * p + 1) * Tn + 2 * c]));
        EB[p] = pk2(__expf(tr[(2 * p) * Tn + 2 * c + 1]),
                    __expf(tr[(2 * p + 1) * Tn + 2 * c + 1]));
    }

    // Emission stream: raw float2 loaded 8 steps ahead; exp'd at step top
    const float2* ep = (const float2*)(em + (size_t)b * Sn * Tn) + c;
    float2 eraw[8];
#pragma unroll
    for (int d = 0; d < 8; d++) eraw[d] = __ldg(ep + d * 32);

    u64 s    = pk2(1.0f, 1.0f);
    int offk = 0;
    __syncwarp();   // one-time: after staging, before the recursion

    for (int tb = 0; tb < Sn; tb += 8) {
#pragma unroll
        for (int u = 0; u < 8; u++) {
            const int t   = tb + u;
            const int par = u & 1;

            // publish own pair (LSU orders the following LDS of this buffer)
            sbuf[w][par][c] = s;

            // independent work covers the STS->LDS pipeline gap
            float2 mm = mrow[w][t];
            float2 er = eraw[u];
            u64 f = pk2(__expf(er.x), __expf(er.y));   // MUFU, used at tail
            if (t + 8 < Sn) eraw[u] = __ldg(ep + (size_t)(t + 8) * 32);

            // matvec for both columns: 16 LDS.128, 64 FFMA2 (4 acc chains)
            const u64* sv = &sbuf[w][par][0];
            u64 a0 = 0, a1 = 0, b0 = 0, b1 = 0;
            u64 v0pair;
#pragma unroll
            for (int p = 0; p < 32; p += 2) {
                ulonglong2 x = *(const ulonglong2*)&sv[p];
                if (p == 0) v0pair = x.x;
                a0 = ffma2(x.x, EA[p + 0], a0);
                b0 = ffma2(x.x, EB[p + 0], b0);
                a1 = ffma2(x.y, EA[p + 1], a1);
                b1 = ffma2(x.y, EB[p + 1], b1);
            }
            u64 sa = fadd2(a0, a1);
            u64 sb = fadd2(b0, b1);
            float2 fa = upk(sa), fb2 = upk(sb);
            u64 qf = fmul2(pk2(fa.x + fa.y, fb2.x + fb2.y), f);

            // masked blend: s = m*qf + (1-m)*s
            u64 sn = ffma2(pk2(mm.y, mm.y), s, fmul2(pk2(mm.x, mm.x), qf));

            // renorm every 8 steps by 2^-ke, ke from exponent of s[0]
            // (v0pair.x = published s[0], uniform across lanes)
            if (u == 7) {
                int ke = ((__float_as_int(upk(v0pair).x) >> 23) & 0xff) - 127;
                offk += ke;
                float sc = __int_as_float((127 - ke) << 23);
                sn = fmul2(sn, pk2(sc, sc));
            }
            s = sn;
        }
    }

    // z[b] = offk*ln2 + log(sum_j s[j])
    float2 sp = upk(s);
    float x = sp.x + sp.y;
#pragma unroll
    for (int o = 16; o; o >>= 1)
        x += __shfl_xor_sync(0xffffffffu, x, o);
    if (lane == 0) {
        double z = (double)offk * 0.6931471805599453 + (double)logf(x);
        g_z[b] = (float)z;
    }
}

// ---------------------------------------------------------------------------
// out = -mean(z - score)
// ---------------------------------------------------------------------------
__global__ __launch_bounds__(Bn) void crf_final(float* __restrict__ out)
{
    __shared__ float red[Bn];
    const int tid = threadIdx.x;
    red[tid] = g_z[tid] - g_sc[tid];
    __syncthreads();
    for (int st = Bn / 2; st; st >>= 1) {
        if (tid < st) red[tid] += red[tid + st];
        __syncthreads();
    }
    if (tid == 0) out[0] = -red[0] / (float)Bn;
}

extern "C" void kernel_launch(void* const* d_in, const int* in_sizes, int n_in,
                              void* d_out, int out_size)
{
    const float* em   = (const float*)d_in[0];  // emissions [B,S,T] f32
    const int*   tags = (const int*)  d_in[1];  // tags [B,S] i32
    const float* mask = (const float*)d_in[2];  // mask [B,S] f32
    const float* tr   = (const float*)d_in[3];  // transitions [T,T] f32

    crf_fused<<<FWD_BLOCKS + GOLD_BLOCKS, 32 * WPB>>>(em, tags, mask, tr);
    crf_final<<<1, Bn>>>((float*)d_out);
}